// round 1
// baseline (speedup 1.0000x reference)
#include <cuda_runtime.h>
#include <math.h>

#define BB 256      // batch
#define TT 512      // time steps
#define FF 128      // input features
#define HH 512      // hidden
#define G4 2048     // 4*HH
#define MT 64       // batch rows per block
#define NTG 16      // gate-cols per block (per gate)
#define KC 32       // K chunk
#define NCHUNK ((HH + FF) / KC)   // 20

// Persistent state (device globals: no allocation allowed)
__device__ float g_h[2][BB * HH];
__device__ float g_c[BB * HH];

__device__ __forceinline__ unsigned f2tf(float f) {
    unsigned u;
    asm("cvt.rna.tf32.f32 %0, %1;" : "=r"(u) : "f"(f));
    return u;
}

__device__ __forceinline__ void mma8(float* c,
                                     unsigned a0, unsigned a1, unsigned a2, unsigned a3,
                                     unsigned b0, unsigned b1) {
    asm volatile(
        "mma.sync.aligned.m16n8k8.row.col.f32.tf32.tf32.f32 "
        "{%0,%1,%2,%3},{%4,%5,%6,%7},{%8,%9},{%0,%1,%2,%3};"
        : "+f"(c[0]), "+f"(c[1]), "+f"(c[2]), "+f"(c[3])
        : "r"(a0), "r"(a1), "r"(a2), "r"(a3), "r"(b0), "r"(b1));
}

__global__ void init_state() {
    int i = blockIdx.x * blockDim.x + threadIdx.x;
    if (i < BB * HH) {
        g_h[0][i] = 0.f;
        g_c[i]    = 0.f;
    }
}

// One LSTM timestep. z = [h_in | x_t] @ [U ; W] + b, then gate update.
// Grid: (BB/MT, HH/NTG) = (4, 32). 256 threads = 8 warps (4 M x 2 N).
// Each warp: 16 rows x 8 gate-cols x 4 gates (4 accumulator frags).
__global__ void __launch_bounds__(256) lstm_step(
    const float* __restrict__ x, const float* __restrict__ W,
    const float* __restrict__ U, const float* __restrict__ bias, int t) {

    const float* h_in  = g_h[t & 1];
    float*       h_out = g_h[(t + 1) & 1];

    __shared__ unsigned As[2][MT][KC + 1];        // [buf][row][k]    (pad 1)
    __shared__ unsigned Bs[2][KC][4 * NTG + 4];   // [buf][k][4 gates x 16 cols] (pad 4)
    __shared__ int rowmask[MT];

    const int tid = threadIdx.x;
    const int rb  = blockIdx.x * MT;   // batch-row base
    const int cb  = blockIdx.y * NTG;  // gate-col base

    // ---- mask: any(x[b,t,:] != -1.0) ----
    if (tid < MT) rowmask[tid] = 0;
    __syncthreads();
    {
        int r = tid >> 2, q = tid & 3;
        const float* xr = x + ((size_t)(rb + r) * TT + t) * FF + q * 32;
        bool any = false;
        #pragma unroll 8
        for (int j = 0; j < 32; ++j) any |= (xr[j] != -1.0f);
        if (any) rowmask[r] = 1;
    }

    // ---- staging indices ----
    const int ar   = tid >> 2;             // 0..63  A row
    const int aseg = (tid & 3) * 8;        // 0,8,16,24 A k-seg
    const int bkr  = tid >> 3;             // 0..31  B k-row
    const int bc0  = (tid & 7) * 8;        // 0..56  B local col seg
    const int bg   = bc0 >> 4;             // gate of this seg
    const int bcol = bg * HH + cb + (bc0 & 15);  // global z column

    const int warp = tid >> 5, lane = tid & 31;
    const int wm = warp >> 1, wn = warp & 1;
    const int gid = lane >> 2, tig = lane & 3;

    float4 av0, av1, bv0, bv1;

#define LOADG(ch)                                                                     \
    do {                                                                              \
        int k0 = (ch) * KC;                                                           \
        const float* asrc = (k0 < HH)                                                 \
            ? (h_in + (size_t)(rb + ar) * HH + k0 + aseg)                             \
            : (x + ((size_t)(rb + ar) * TT + t) * FF + (k0 - HH) + aseg);             \
        av0 = *(const float4*)asrc;                                                   \
        av1 = *(const float4*)(asrc + 4);                                             \
        const float* bsrc = (k0 < HH)                                                 \
            ? (U + (size_t)(k0 + bkr) * G4 + bcol)                                    \
            : (W + (size_t)(k0 - HH + bkr) * G4 + bcol);                              \
        bv0 = *(const float4*)bsrc;                                                   \
        bv1 = *(const float4*)(bsrc + 4);                                             \
    } while (0)

#define STORES(bf)                                                                    \
    do {                                                                              \
        As[bf][ar][aseg + 0] = f2tf(av0.x); As[bf][ar][aseg + 1] = f2tf(av0.y);       \
        As[bf][ar][aseg + 2] = f2tf(av0.z); As[bf][ar][aseg + 3] = f2tf(av0.w);       \
        As[bf][ar][aseg + 4] = f2tf(av1.x); As[bf][ar][aseg + 5] = f2tf(av1.y);       \
        As[bf][ar][aseg + 6] = f2tf(av1.z); As[bf][ar][aseg + 7] = f2tf(av1.w);       \
        Bs[bf][bkr][bc0 + 0] = f2tf(bv0.x); Bs[bf][bkr][bc0 + 1] = f2tf(bv0.y);       \
        Bs[bf][bkr][bc0 + 2] = f2tf(bv0.z); Bs[bf][bkr][bc0 + 3] = f2tf(bv0.w);       \
        Bs[bf][bkr][bc0 + 4] = f2tf(bv1.x); Bs[bf][bkr][bc0 + 5] = f2tf(bv1.y);       \
        Bs[bf][bkr][bc0 + 6] = f2tf(bv1.z); Bs[bf][bkr][bc0 + 7] = f2tf(bv1.w);       \
    } while (0)

    float acc[4][4] = {{0.f, 0.f, 0.f, 0.f}, {0.f, 0.f, 0.f, 0.f},
                       {0.f, 0.f, 0.f, 0.f}, {0.f, 0.f, 0.f, 0.f}};

    LOADG(0);
    STORES(0);

    for (int ch = 0; ch < NCHUNK; ++ch) {
        __syncthreads();  // smem[ch&1] ready for all warps
        const int buf = ch & 1;
        if (ch + 1 < NCHUNK) LOADG(ch + 1);

        #pragma unroll
        for (int ks = 0; ks < KC / 8; ++ks) {
            const int k = ks * 8;
            unsigned a0 = As[buf][wm * 16 + gid][k + tig];
            unsigned a1 = As[buf][wm * 16 + gid + 8][k + tig];
            unsigned a2 = As[buf][wm * 16 + gid][k + tig + 4];
            unsigned a3 = As[buf][wm * 16 + gid + 8][k + tig + 4];
            #pragma unroll
            for (int g = 0; g < 4; ++g) {
                const int nb = g * NTG + wn * 8 + gid;
                unsigned b0 = Bs[buf][k + tig][nb];
                unsigned b1 = Bs[buf][k + tig + 4][nb];
                mma8(acc[g], a0, a1, a2, a3, b0, b1);
            }
        }
        __syncthreads();  // all warps done with buf^1's previous contents
        if (ch + 1 < NCHUNK) STORES((ch + 1) & 1);
    }

    // ---- epilogue: gates + state update ----
    #pragma unroll
    for (int ii = 0; ii < 2; ++ii) {
        #pragma unroll
        for (int jj = 0; jj < 2; ++jj) {
            const int idx = ii * 2 + jj;
            const int lr  = wm * 16 + gid + ii * 8;
            const int row = rb + lr;
            const int j   = cb + wn * 8 + 2 * tig + jj;

            float zi = acc[0][idx] + bias[j];
            float zf = acc[1][idx] + bias[HH + j];
            float zg = acc[2][idx] + bias[2 * HH + j];
            float zo = acc[3][idx] + bias[3 * HH + j];

            float iv = 1.f / (1.f + expf(-zi));
            float fv = 1.f / (1.f + expf(-zf));
            float gv = fmaxf(zg, 0.f);
            float ov = 1.f / (1.f + expf(-zo));

            const int off = row * HH + j;
            float cold = g_c[off];
            float cnew = fv * cold + iv * gv;
            float hnew = ov * fmaxf(cnew, 0.f);

            if (rowmask[lr]) {
                g_c[off]   = cnew;
                h_out[off] = hnew;
            } else {
                h_out[off] = h_in[off];   // carry h forward into the ping-pong buffer
            }
        }
    }
#undef LOADG
#undef STORES
}

// out[b] = sigmoid(h[b,:] @ Wd + bd). Final h lives in g_h[0] (512 steps, even).
__global__ void head_kernel(const float* __restrict__ Wd, const float* __restrict__ bd,
                            float* __restrict__ out) {
    const float* h = g_h[0];
    const int warp = threadIdx.x >> 5, lane = threadIdx.x & 31;
    const int row = blockIdx.x * 8 + warp;
    float s = 0.f;
    #pragma unroll
    for (int k = lane; k < HH; k += 32) s += h[row * HH + k] * Wd[k];
    #pragma unroll
    for (int o = 16; o; o >>= 1) s += __shfl_xor_sync(0xffffffffu, s, o);
    if (lane == 0) out[row] = 1.f / (1.f + expf(-(s + bd[0])));
}

extern "C" void kernel_launch(void* const* d_in, const int* in_sizes, int n_in,
                              void* d_out, int out_size) {
    const float* x  = (const float*)d_in[0];
    const float* W  = (const float*)d_in[1];
    const float* U  = (const float*)d_in[2];
    const float* b  = (const float*)d_in[3];
    const float* Wd = (const float*)d_in[4];
    const float* bd = (const float*)d_in[5];

    init_state<<<(BB * HH + 255) / 256, 256>>>();

    dim3 grid(BB / MT, HH / NTG);  // (4, 32) = 128 blocks
    for (int t = 0; t < TT; ++t)
        lstm_step<<<grid, 256>>>(x, W, U, b, t);

    head_kernel<<<BB / 8, 256>>>(Wd, bd, (float*)d_out);
}

// round 2
// speedup vs baseline: 1.0006x; 1.0006x over previous
#include <cuda_runtime.h>
#include <math.h>

#define BB 256      // batch
#define TT 512      // time steps
#define FF 128      // input features
#define HH 512      // hidden
#define G4 2048     // 4*HH
#define MT 64       // batch rows per block
#define NTG 16      // gate-cols per block (per gate)
#define KC 32       // K chunk
#define NCHUNK ((HH + FF) / KC)   // 20

// Persistent state (device globals: no allocation allowed)
__device__ float g_h[2][BB * HH];
__device__ float g_c[BB * HH];

__device__ __forceinline__ unsigned f2tf(float f) {
    unsigned u;
    asm("cvt.rna.tf32.f32 %0, %1;" : "=r"(u) : "f"(f));
    return u;
}

__device__ __forceinline__ void mma8(float* c,
                                     unsigned a0, unsigned a1, unsigned a2, unsigned a3,
                                     unsigned b0, unsigned b1) {
    asm volatile(
        "mma.sync.aligned.m16n8k8.row.col.f32.tf32.tf32.f32 "
        "{%0,%1,%2,%3},{%4,%5,%6,%7},{%8,%9},{%0,%1,%2,%3};"
        : "+f"(c[0]), "+f"(c[1]), "+f"(c[2]), "+f"(c[3])
        : "r"(a0), "r"(a1), "r"(a2), "r"(a3), "r"(b0), "r"(b1));
}

__global__ void init_state() {
    int i = blockIdx.x * blockDim.x + threadIdx.x;
    if (i < BB * HH) {
        g_h[0][i] = 0.f;
        g_c[i]    = 0.f;
    }
}

// One LSTM timestep. z = [h_in | x_t] @ [U ; W] + b, then gate update.
// Grid: (BB/MT, HH/NTG) = (4, 32). 256 threads = 8 warps (4 M x 2 N).
// Each warp: 16 rows x 8 gate-cols x 4 gates (4 accumulator frags).
__global__ void __launch_bounds__(256) lstm_step(
    const float* __restrict__ x, const float* __restrict__ W,
    const float* __restrict__ U, const float* __restrict__ bias, int t) {

    const float* h_in  = g_h[t & 1];
    float*       h_out = g_h[(t + 1) & 1];

    __shared__ unsigned As[2][MT][KC + 1];        // [buf][row][k]    (pad 1)
    __shared__ unsigned Bs[2][KC][4 * NTG + 4];   // [buf][k][4 gates x 16 cols] (pad 4)
    __shared__ int rowmask[MT];

    const int tid = threadIdx.x;
    const int rb  = blockIdx.x * MT;   // batch-row base
    const int cb  = blockIdx.y * NTG;  // gate-col base

    // ---- mask: any(x[b,t,:] != -1.0) ----
    if (tid < MT) rowmask[tid] = 0;
    __syncthreads();
    {
        int r = tid >> 2, q = tid & 3;
        const float* xr = x + ((size_t)(rb + r) * TT + t) * FF + q * 32;
        bool any = false;
        #pragma unroll 8
        for (int j = 0; j < 32; ++j) any |= (xr[j] != -1.0f);
        if (any) rowmask[r] = 1;
    }

    // ---- staging indices ----
    const int ar   = tid >> 2;             // 0..63  A row
    const int aseg = (tid & 3) * 8;        // 0,8,16,24 A k-seg
    const int bkr  = tid >> 3;             // 0..31  B k-row
    const int bc0  = (tid & 7) * 8;        // 0..56  B local col seg
    const int bg   = bc0 >> 4;             // gate of this seg
    const int bcol = bg * HH + cb + (bc0 & 15);  // global z column

    const int warp = tid >> 5, lane = tid & 31;
    const int wm = warp >> 1, wn = warp & 1;
    const int gid = lane >> 2, tig = lane & 3;

    float4 av0, av1, bv0, bv1;

#define LOADG(ch)                                                                     \
    do {                                                                              \
        int k0 = (ch) * KC;                                                           \
        const float* asrc = (k0 < HH)                                                 \
            ? (h_in + (size_t)(rb + ar) * HH + k0 + aseg)                             \
            : (x + ((size_t)(rb + ar) * TT + t) * FF + (k0 - HH) + aseg);             \
        av0 = *(const float4*)asrc;                                                   \
        av1 = *(const float4*)(asrc + 4);                                             \
        const float* bsrc = (k0 < HH)                                                 \
            ? (U + (size_t)(k0 + bkr) * G4 + bcol)                                    \
            : (W + (size_t)(k0 - HH + bkr) * G4 + bcol);                              \
        bv0 = *(const float4*)bsrc;                                                   \
        bv1 = *(const float4*)(bsrc + 4);                                             \
    } while (0)

#define STORES(bf)                                                                    \
    do {                                                                              \
        As[bf][ar][aseg + 0] = f2tf(av0.x); As[bf][ar][aseg + 1] = f2tf(av0.y);       \
        As[bf][ar][aseg + 2] = f2tf(av0.z); As[bf][ar][aseg + 3] = f2tf(av0.w);       \
        As[bf][ar][aseg + 4] = f2tf(av1.x); As[bf][ar][aseg + 5] = f2tf(av1.y);       \
        As[bf][ar][aseg + 6] = f2tf(av1.z); As[bf][ar][aseg + 7] = f2tf(av1.w);       \
        Bs[bf][bkr][bc0 + 0] = f2tf(bv0.x); Bs[bf][bkr][bc0 + 1] = f2tf(bv0.y);       \
        Bs[bf][bkr][bc0 + 2] = f2tf(bv0.z); Bs[bf][bkr][bc0 + 3] = f2tf(bv0.w);       \
        Bs[bf][bkr][bc0 + 4] = f2tf(bv1.x); Bs[bf][bkr][bc0 + 5] = f2tf(bv1.y);       \
        Bs[bf][bkr][bc0 + 6] = f2tf(bv1.z); Bs[bf][bkr][bc0 + 7] = f2tf(bv1.w);       \
    } while (0)

    float acc[4][4] = {{0.f, 0.f, 0.f, 0.f}, {0.f, 0.f, 0.f, 0.f},
                       {0.f, 0.f, 0.f, 0.f}, {0.f, 0.f, 0.f, 0.f}};

    LOADG(0);
    STORES(0);

    for (int ch = 0; ch < NCHUNK; ++ch) {
        __syncthreads();  // smem[ch&1] ready for all warps
        const int buf = ch & 1;
        if (ch + 1 < NCHUNK) LOADG(ch + 1);

        #pragma unroll
        for (int ks = 0; ks < KC / 8; ++ks) {
            const int k = ks * 8;
            unsigned a0 = As[buf][wm * 16 + gid][k + tig];
            unsigned a1 = As[buf][wm * 16 + gid + 8][k + tig];
            unsigned a2 = As[buf][wm * 16 + gid][k + tig + 4];
            unsigned a3 = As[buf][wm * 16 + gid + 8][k + tig + 4];
            #pragma unroll
            for (int g = 0; g < 4; ++g) {
                const int nb = g * NTG + wn * 8 + gid;
                unsigned b0 = Bs[buf][k + tig][nb];
                unsigned b1 = Bs[buf][k + tig + 4][nb];
                mma8(acc[g], a0, a1, a2, a3, b0, b1);
            }
        }
        __syncthreads();  // all warps done with buf^1's previous contents
        if (ch + 1 < NCHUNK) STORES((ch + 1) & 1);
    }

    // ---- epilogue: gates + state update ----
    #pragma unroll
    for (int ii = 0; ii < 2; ++ii) {
        #pragma unroll
        for (int jj = 0; jj < 2; ++jj) {
            const int idx = ii * 2 + jj;
            const int lr  = wm * 16 + gid + ii * 8;
            const int row = rb + lr;
            const int j   = cb + wn * 8 + 2 * tig + jj;

            float zi = acc[0][idx] + bias[j];
            float zf = acc[1][idx] + bias[HH + j];
            float zg = acc[2][idx] + bias[2 * HH + j];
            float zo = acc[3][idx] + bias[3 * HH + j];

            float iv = 1.f / (1.f + expf(-zi));
            float fv = 1.f / (1.f + expf(-zf));
            float gv = fmaxf(zg, 0.f);
            float ov = 1.f / (1.f + expf(-zo));

            const int off = row * HH + j;
            float cold = g_c[off];
            float cnew = fv * cold + iv * gv;
            float hnew = ov * fmaxf(cnew, 0.f);

            if (rowmask[lr]) {
                g_c[off]   = cnew;
                h_out[off] = hnew;
            } else {
                h_out[off] = h_in[off];   // carry h forward into the ping-pong buffer
            }
        }
    }
#undef LOADG
#undef STORES
}

// out[b] = sigmoid(h[b,:] @ Wd + bd). Final h lives in g_h[0] (512 steps, even).
__global__ void head_kernel(const float* __restrict__ Wd, const float* __restrict__ bd,
                            float* __restrict__ out) {
    const float* h = g_h[0];
    const int warp = threadIdx.x >> 5, lane = threadIdx.x & 31;
    const int row = blockIdx.x * 8 + warp;
    float s = 0.f;
    #pragma unroll
    for (int k = lane; k < HH; k += 32) s += h[row * HH + k] * Wd[k];
    #pragma unroll
    for (int o = 16; o; o >>= 1) s += __shfl_xor_sync(0xffffffffu, s, o);
    if (lane == 0) out[row] = 1.f / (1.f + expf(-(s + bd[0])));
}

extern "C" void kernel_launch(void* const* d_in, const int* in_sizes, int n_in,
                              void* d_out, int out_size) {
    const float* x  = (const float*)d_in[0];
    const float* W  = (const float*)d_in[1];
    const float* U  = (const float*)d_in[2];
    const float* b  = (const float*)d_in[3];
    const float* Wd = (const float*)d_in[4];
    const float* bd = (const float*)d_in[5];

    init_state<<<(BB * HH + 255) / 256, 256>>>();

    dim3 grid(BB / MT, HH / NTG);  // (4, 32) = 128 blocks
    for (int t = 0; t < TT; ++t)
        lstm_step<<<grid, 256>>>(x, W, U, b, t);

    head_kernel<<<BB / 8, 256>>>(Wd, bd, (float*)d_out);
}

// round 4
// speedup vs baseline: 3.1428x; 3.1409x over previous
#include <cuda_runtime.h>

#define BB 256
#define TT 512
#define FF 128
#define HH 512
#define G4 2048
#define NBLK 128
#define ASTR 68
#define ABUF (64 * ASTR)
#define ZSTR 68

__device__ float g_h[2][BB * HH];
__device__ float g_zx[(size_t)TT * BB * 64 * 32];   // [t][cbi][b][64]
__device__ unsigned char g_mask[TT * BB];
__device__ unsigned g_cnt;

#define U32 __float_as_uint

__device__ __forceinline__ unsigned f2tf(float f) {
    unsigned u; asm("cvt.rna.tf32.f32 %0, %1;" : "=r"(u) : "f"(f)); return u;
}
__device__ __forceinline__ float sigf(float x) {
    float t; asm("tanh.approx.f32 %0, %1;" : "=f"(t) : "f"(x * 0.5f));
    return fmaf(t, 0.5f, 0.5f);
}
__device__ __forceinline__ void cpa(unsigned d, const float* g) {
    asm volatile("cp.async.cg.shared.global [%0],[%1],16;" :: "r"(d), "l"(g) : "memory");
}
__device__ __forceinline__ void cp_commit() { asm volatile("cp.async.commit_group;" ::: "memory"); }
template <int N> __device__ __forceinline__ void cp_wait() {
    asm volatile("cp.async.wait_group %0;" :: "n"(N) : "memory");
}
__device__ __forceinline__ void mma8(float* c, unsigned a0, unsigned a1, unsigned a2,
                                     unsigned a3, unsigned b0, unsigned b1) {
    asm volatile(
        "mma.sync.aligned.m16n8k8.row.col.f32.tf32.tf32.f32 "
        "{%0,%1,%2,%3},{%4,%5,%6,%7},{%8,%9},{%0,%1,%2,%3};"
        : "+f"(c[0]), "+f"(c[1]), "+f"(c[2]), "+f"(c[3])
        : "r"(a0), "r"(a1), "r"(a2), "r"(a3), "r"(b0), "r"(b1));
}

__global__ void zero_cnt() { g_cnt = 0u; }

__global__ void mask_kernel(const float* __restrict__ x) {
    int wid = (blockIdx.x * blockDim.x + threadIdx.x) >> 5;
    int lane = threadIdx.x & 31;
    int b = wid >> 9, t = wid & 511;
    float4 v = *(const float4*)(x + (size_t)wid * FF + lane * 4);
    bool any = (v.x != -1.f) | (v.y != -1.f) | (v.z != -1.f) | (v.w != -1.f);
    unsigned m = __ballot_sync(0xffffffffu, any);
    if (lane == 0) g_mask[t * BB + b] = (m != 0u);
}

// zx = x@W + b. Block: 128 t-rows (one b) x 64 z-cols (one cbi). K=128.
__global__ void __launch_bounds__(128) zx_gemm(const float* __restrict__ x,
                                               const float* __restrict__ W,
                                               const float* __restrict__ bias) {
    extern __shared__ float sm[];
    float* xs = sm;             // [128][132]
    float* ws = sm + 16896;     // [128][72]
    const int tid = threadIdx.x;
    const int b = blockIdx.x >> 2, tt = blockIdx.x & 3, cbi = blockIdx.y;
    const int hc0 = cbi * 16;
    const unsigned xsA = (unsigned)__cvta_generic_to_shared(xs);
    const unsigned wsA = (unsigned)__cvta_generic_to_shared(ws);

    #pragma unroll 4
    for (int q = 0; q < 32; ++q) {
        int fi = q * 128 + tid, r = fi >> 5, s = (fi & 31) * 4;
        cpa(xsA + (r * 132 + s) * 4, x + ((size_t)b * TT + tt * 128 + r) * FF + s);
    }
    #pragma unroll 4
    for (int q = 0; q < 16; ++q) {
        int fi = q * 128 + tid, k = fi >> 4, c = (fi & 15) * 4;
        cpa(wsA + (k * 72 + c) * 4, W + (size_t)k * G4 + (c >> 4) * HH + hc0 + (c & 15));
    }
    cp_commit(); cp_wait<0>(); __syncthreads();

    const int warp = tid >> 5, lane = tid & 31;
    const int gid = lane >> 2, tg = lane & 3;
    float acc[2][8][4];
    #pragma unroll
    for (int m = 0; m < 2; ++m)
        #pragma unroll
        for (int n = 0; n < 8; ++n)
            #pragma unroll
            for (int q = 0; q < 4; ++q) acc[m][n][q] = 0.f;

    #pragma unroll
    for (int k8 = 0; k8 < 16; ++k8) {
        float a[2][4];
        #pragma unroll
        for (int mt = 0; mt < 2; ++mt) {
            int base = (warp * 32 + mt * 16 + gid) * 132 + k8 * 8 + tg;
            a[mt][0] = xs[base];           a[mt][1] = xs[base + 8 * 132];
            a[mt][2] = xs[base + 4];       a[mt][3] = xs[base + 8 * 132 + 4];
        }
        #pragma unroll
        for (int nt = 0; nt < 8; ++nt) {
            float b0 = ws[(k8 * 8 + tg) * 72 + nt * 8 + gid];
            float b1 = ws[(k8 * 8 + tg + 4) * 72 + nt * 8 + gid];
            #pragma unroll
            for (int mt = 0; mt < 2; ++mt)
                mma8(acc[mt][nt], U32(a[mt][0]), U32(a[mt][1]), U32(a[mt][2]),
                     U32(a[mt][3]), U32(b0), U32(b1));
        }
    }
    #pragma unroll
    for (int mt = 0; mt < 2; ++mt)
        #pragma unroll
        for (int hi = 0; hi < 2; ++hi) {
            int r = warp * 32 + mt * 16 + gid + hi * 8;
            int t = tt * 128 + r;
            #pragma unroll
            for (int nt = 0; nt < 8; ++nt) {
                int c = nt * 8 + 2 * tg;
                int gc = (c >> 4) * HH + hc0 + (c & 15);
                float2 o = make_float2(acc[mt][nt][hi * 2 + 0] + __ldg(bias + gc),
                                       acc[mt][nt][hi * 2 + 1] + __ldg(bias + gc + 1));
                *(float2*)&g_zx[(((size_t)t * 32 + cbi) * BB + b) * 64 + c] = o;
            }
        }
}

// Persistent recurrent kernel: 128 blocks x 128 threads, all 512 steps.
__global__ void __launch_bounds__(128, 1) lstm_persist(const float* __restrict__ U) {
    extern __shared__ float sm[];
    float4* Us4 = (float4*)sm;            // 32768 floats: packed B-frags
    float* As = sm + 32768;               // 2 x 64 x ASTR
    float* Zs = As + 2 * ABUF;            // 64 x ZSTR
    float* zb = Zs + 64 * ZSTR;           // [2][2][32][24]

    const int tid = threadIdx.x;
    const int rb = (blockIdx.x & 3) * 64, cbi = blockIdx.x >> 2, hc0 = cbi * 16;
    const int warp = tid >> 5, lane = tid & 31;
    const int wm = warp >> 1, wn = warp & 1;
    const int gid = lane >> 2, tg = lane & 3;
    const unsigned AsA = (unsigned)__cvta_generic_to_shared(As);
    const unsigned ZsA = (unsigned)__cvta_generic_to_shared(Zs);

    // --- pack U slice into B-fragment order (tf32) ---
    for (int idx = tid; idx < 64 * HH; idx += 128) {
        int k = idx >> 6, c = idx & 63;
        int gcol = (c >> 4) * HH + hc0 + (c & 15);
        unsigned v = f2tf(__ldg(&U[(size_t)k * G4 + gcol]));
        int n8 = c >> 3, g = c & 7, k8 = k >> 3, kk = k & 7;
        int f = k8 >> 1, slot = (k8 & 1) * 2 + (kk >> 2), ln = g * 4 + (kk & 3);
        sm[(((n8 * 32 + f) * 32 + ln) << 2) + slot] = __uint_as_float(v);
    }
    for (int idx = tid; idx < 64 * 16; idx += 128)
        g_h[0][(size_t)(rb + (idx >> 4)) * HH + hc0 + (idx & 15)] = 0.f;

    unsigned tgt = 0;
#define GRID_BAR()                                                        \
    do {                                                                  \
        __syncthreads();                                                  \
        tgt += NBLK;                                                      \
        if (tid == 0) {                                                   \
            __threadfence();                                              \
            atomicAdd(&g_cnt, 1u);                                        \
            while (*(volatile unsigned*)&g_cnt < tgt) {                   \
                asm volatile("nanosleep.u32 64;");                        \
            }                                                             \
            __threadfence();                                              \
        }                                                                 \
        __syncthreads();                                                  \
    } while (0)

    GRID_BAR();  // h[0] zeroed everywhere

    float cR[16], hR[16];
    #pragma unroll
    for (int i = 0; i < 16; ++i) { cR[i] = 0.f; hR[i] = 0.f; }

    for (int t = 0; t < TT; ++t) {
        const float* hin = g_h[t & 1];
        float* hout = g_h[(t + 1) & 1];
        const float* zsrc = g_zx + (((size_t)t * 32 + cbi) * BB + rb) * 64;

        #pragma unroll
        for (int q = 0; q < 8; ++q) {   // stage zx tile (16KB contiguous)
            int fi = q * 128 + tid, r = fi >> 4, s = (fi & 15) * 4;
            cpa(ZsA + (r * ZSTR + s) * 4, zsrc + r * 64 + s);
        }
        cp_commit();

#define STAGE_A(ch)                                                             \
        do {                                                                    \
            unsigned dst = AsA + ((ch) & 1) * ABUF * 4;                         \
            _Pragma("unroll")                                                   \
            for (int q = 0; q < 8; ++q) {                                       \
                int fi = q * 128 + tid, r = fi >> 4, s = (fi & 15) * 4;         \
                cpa(dst + (r * ASTR + s) * 4,                                   \
                    hin + (size_t)(rb + r) * HH + (ch) * 64 + s);               \
            }                                                                   \
        } while (0)

        STAGE_A(0); cp_commit();

        float acc[2][4][4];
        #pragma unroll
        for (int m = 0; m < 2; ++m)
            #pragma unroll
            for (int n = 0; n < 4; ++n)
                #pragma unroll
                for (int q = 0; q < 4; ++q) acc[m][n][q] = 0.f;

        for (int ch = 0; ch < 8; ++ch) {
            if (ch + 1 < 8) STAGE_A(ch + 1);
            cp_commit();
            cp_wait<1>(); __syncthreads();
            const float* Ab = As + (ch & 1) * ABUF;
            #pragma unroll
            for (int fl = 0; fl < 4; ++fl) {
                float a[2][2][4];
                #pragma unroll
                for (int e = 0; e < 2; ++e) {
                    int kl = (fl * 2 + e) * 8;
                    #pragma unroll
                    for (int mt = 0; mt < 2; ++mt) {
                        int base = (wm * 32 + mt * 16 + gid) * ASTR + kl + tg;
                        a[e][mt][0] = Ab[base];      a[e][mt][1] = Ab[base + 8 * ASTR];
                        a[e][mt][2] = Ab[base + 4];  a[e][mt][3] = Ab[base + 8 * ASTR + 4];
                    }
                }
                #pragma unroll
                for (int nt = 0; nt < 4; ++nt) {
                    float4 bq = Us4[((wn * 4 + nt) * 32 + ch * 4 + fl) * 32 + lane];
                    #pragma unroll
                    for (int mt = 0; mt < 2; ++mt) {
                        mma8(acc[mt][nt], U32(a[0][mt][0]), U32(a[0][mt][1]),
                             U32(a[0][mt][2]), U32(a[0][mt][3]), U32(bq.x), U32(bq.y));
                        mma8(acc[mt][nt], U32(a[1][mt][0]), U32(a[1][mt][1]),
                             U32(a[1][mt][2]), U32(a[1][mt][3]), U32(bq.z), U32(bq.w));
                    }
                }
            }
            __syncthreads();
        }
        cp_wait<0>();

        // --- epilogue ---
        if (wn == 1) {  // gates g,o -> zb
            #pragma unroll
            for (int mt = 0; mt < 2; ++mt)
                #pragma unroll
                for (int nt = 0; nt < 4; ++nt)
                    #pragma unroll
                    for (int cq = 0; cq < 4; ++cq) {
                        int rl = mt * 16 + gid + ((cq >> 1) ? 8 : 0);
                        int g2 = nt >> 1, j = (nt & 1) * 8 + 2 * tg + (cq & 1);
                        float z = acc[mt][nt][cq] +
                                  Zs[(wm * 32 + rl) * ZSTR + (2 + g2) * 16 + j];
                        zb[((wm * 2 + g2) * 32 + rl) * 24 + j] = z;
                    }
        }
        __syncthreads();
        if (wn == 0) {
            bool mk[4];
            #pragma unroll
            for (int mt = 0; mt < 2; ++mt)
                #pragma unroll
                for (int hi = 0; hi < 2; ++hi)
                    mk[mt * 2 + hi] =
                        g_mask[t * BB + rb + wm * 32 + mt * 16 + gid + hi * 8] != 0;
            #pragma unroll
            for (int mt = 0; mt < 2; ++mt)
                #pragma unroll
                for (int jh = 0; jh < 2; ++jh)
                    #pragma unroll
                    for (int cq = 0; cq < 4; ++cq) {
                        int hi = cq >> 1, rl = mt * 16 + gid + hi * 8;
                        int row = wm * 32 + rl, grow = rb + row;
                        int j = jh * 8 + 2 * tg + (cq & 1);
                        float zi = acc[mt][jh][cq] + Zs[row * ZSTR + j];
                        float zf = acc[mt][2 + jh][cq] + Zs[row * ZSTR + 16 + j];
                        float zg = zb[((wm * 2 + 0) * 32 + rl) * 24 + j];
                        float zo = zb[((wm * 2 + 1) * 32 + rl) * 24 + j];
                        float iv = sigf(zi), fv = sigf(zf);
                        float gv = fmaxf(zg, 0.f), ov = sigf(zo);
                        int s = mt * 8 + jh * 4 + cq;
                        float cn = fv * cR[s] + iv * gv;
                        float hn = ov * fmaxf(cn, 0.f);
                        bool m = mk[mt * 2 + hi];
                        cR[s] = m ? cn : cR[s];
                        float hv = m ? hn : hR[s];
                        hR[s] = hv;
                        hout[(size_t)grow * HH + hc0 + j] = hv;
                    }
        }
        GRID_BAR();
    }
#undef STAGE_A
#undef GRID_BAR
}

__global__ void head_kernel(const float* __restrict__ Wd, const float* __restrict__ bd,
                            float* __restrict__ out) {
    const float* h = g_h[0];
    const int warp = threadIdx.x >> 5, lane = threadIdx.x & 31;
    const int row = blockIdx.x * 8 + warp;
    float s = 0.f;
    #pragma unroll
    for (int k = lane; k < HH; k += 32) s += h[row * HH + k] * Wd[k];
    #pragma unroll
    for (int o = 16; o; o >>= 1) s += __shfl_xor_sync(0xffffffffu, s, o);
    if (lane == 0) out[row] = sigf(s + bd[0]);
}

extern "C" void kernel_launch(void* const* d_in, const int* in_sizes, int n_in,
                              void* d_out, int out_size) {
    const float* x  = (const float*)d_in[0];
    const float* W  = (const float*)d_in[1];
    const float* U  = (const float*)d_in[2];
    const float* b  = (const float*)d_in[3];
    const float* Wd = (const float*)d_in[4];
    const float* bd = (const float*)d_in[5];

    cudaFuncSetAttribute(zx_gemm, cudaFuncAttributeMaxDynamicSharedMemorySize, 104448);
    cudaFuncSetAttribute(lstm_persist, cudaFuncAttributeMaxDynamicSharedMemorySize, 195584);

    mask_kernel<<<BB * TT / 8, 256>>>(x);
    zx_gemm<<<dim3(BB * 4, 32), 128, 104448>>>(x, W, b);
    zero_cnt<<<1, 1>>>();
    lstm_persist<<<NBLK, 128, 195584>>>(U);
    head_kernel<<<BB / 8, 256>>>(Wd, bd, (float*)d_out);
}